// round 14
// baseline (speedup 1.0000x reference)
#include <cuda_runtime.h>
#include <cuda_fp16.h>
#include <cstdint>

// ============================================================================
// LSTM cell, base sm_103 ISA. fp16 mma.sync m16n8k16, cp.async 6-slot TK=32,
// ONE barrier per TWO k-chunks (distance-4 slot reuse makes it provably safe),
// fragment-packed operands, register double-buffered fragments with
// cross-stage prefetch. CTA 128x128, 128 threads, warp tile 64x64, 2 CTAs/SM.
// Fused gate epilogue (fast sigmoid/tanh).
//
// z[4096, 8192] = A[4096, 4096] @ B[4096, 8192]
//   A = [x | h], B[k][4u+g] = W{x,h}{f,i,o,g}[k][u]  (gate-interleaved)
// ============================================================================

#define MTOT 4096
#define KTOT 4096
#define NTOT 8192
#define UDIM 2048

#define TM 128
#define TN 128
#define NTHREADS 128

#define MBTOT 256              // MTOT/16
#define NBPTOT 512             // NTOT/16 (n-fragment pairs)
#define K16TOT 256             // KTOT/16
#define CHUNKS 128             // TK=32 chunks (2 k16 each)

#define AK16 (MBTOT * 128)     // uint32 stride per k16 in g_Ap
#define BK16 (NBPTOT * 128)    // uint32 stride per k16 in g_Bp

#define SA_STAGE 8192          // 2 k16 * 8 mb * 512 B
#define SB_STAGE 8192          // 2 k16 * 8 nbp * 512 B
#define STAGE_BYTES (SA_STAGE + SB_STAGE)      // 16384
#define NSLOTS 6
#define PIPE_BYTES (NSLOTS * STAGE_BYTES)      // 98304
#define ZLD 132                                 // z tile: 128*132*4 = 67584
#define SMEM_BYTES PIPE_BYTES

// Fragment-packed fp16 operands (uint32 = f16x2).
static __device__ __align__(16) uint32_t g_Ap[(size_t)K16TOT * AK16];  // 32 MB
static __device__ __align__(16) uint32_t g_Bp[(size_t)K16TOT * BK16];  // 64 MB

// ---------------------------------------------------------------- helpers
__device__ __forceinline__ uint32_t smem_u32(const void* p) {
    uint32_t a;
    asm("{ .reg .u64 t; cvta.to.shared.u64 t, %1; cvt.u32.u64 %0, t; }"
        : "=r"(a) : "l"(p));
    return a;
}

__device__ __forceinline__ uint32_t packh2(float lo, float hi) {
    __half2 h = __floats2half2_rn(lo, hi);
    return *reinterpret_cast<uint32_t*>(&h);
}

__device__ __forceinline__ void cp16(uint32_t dst, const void* src) {
    asm volatile("cp.async.cg.shared.global [%0], [%1], 16;"
                 :: "r"(dst), "l"(src) : "memory");
}
__device__ __forceinline__ void cp_commit() {
    asm volatile("cp.async.commit_group;" ::: "memory");
}
template <int N>
__device__ __forceinline__ void cp_wait() {
    asm volatile("cp.async.wait_group %0;" :: "n"(N) : "memory");
}

__device__ __forceinline__ void mma16(float* d, const uint32_t* a, const uint32_t* b) {
    asm volatile(
        "mma.sync.aligned.m16n8k16.row.col.f32.f16.f16.f32 "
        "{%0,%1,%2,%3}, {%4,%5,%6,%7}, {%8,%9}, {%0,%1,%2,%3};"
        : "+f"(d[0]), "+f"(d[1]), "+f"(d[2]), "+f"(d[3])
        : "r"(a[0]), "r"(a[1]), "r"(a[2]), "r"(a[3]), "r"(b[0]), "r"(b[1]));
}

__device__ __forceinline__ void lds128(uint32_t* r, uint32_t addr) {
    asm volatile("ld.shared.v4.b32 {%0,%1,%2,%3}, [%4];"
                 : "=r"(r[0]), "=r"(r[1]), "=r"(r[2]), "=r"(r[3]) : "r"(addr));
}

__device__ __forceinline__ float fsig(float z) {
    return __fdividef(1.f, 1.f + __expf(-z));
}
__device__ __forceinline__ float ftanh(float z) {
    return __fmaf_rn(2.f, __fdividef(1.f, 1.f + __expf(-2.f * z)), -1.f);
}

// ---------------------------------------------------------------- prepasses
#define NA_BLOCKS 8192
#define NW_BLOCKS 8192
#define WLD 65

__device__ void pack_A_body(const float* __restrict__ x,
                            const float* __restrict__ h, int blk)
{
    uint32_t t = blk * 256 + threadIdx.x;
    int lane = t & 31;
    int mb = (t >> 5) & 255;
    int k16 = t >> 13;                   // 0..255
    int kq = lane & 3, gq = lane >> 2;
    int m = mb * 16 + gq;
    int k = k16 * 16 + 2 * kq;
    const float* src = (k < UDIM) ? (x + k) : (h + (k - UDIM));
    float2 p0 = *(const float2*)(src + (size_t)m * UDIM);
    float2 p1 = *(const float2*)(src + (size_t)(m + 8) * UDIM);
    float2 p2 = *(const float2*)(src + (size_t)m * UDIM + 8);
    float2 p3 = *(const float2*)(src + (size_t)(m + 8) * UDIM + 8);
    uint4 u;
    u.x = packh2(p0.x, p0.y);
    u.y = packh2(p1.x, p1.y);
    u.z = packh2(p2.x, p2.y);
    u.w = packh2(p3.x, p3.y);
    *(uint4*)(g_Ap + (size_t)t * 4) = u;
}

__device__ void pack_W_body(
    float* s_w,
    const float* __restrict__ wxf, const float* __restrict__ wxi,
    const float* __restrict__ wxo, const float* __restrict__ wxg,
    const float* __restrict__ whf, const float* __restrict__ whi,
    const float* __restrict__ who, const float* __restrict__ whg, int blk)
{
    const int tid = threadIdx.x;
    const int kb = blk & 255;                // 256 k16 blocks
    const int ub = blk >> 8;                 // 32 unit-blocks of 64
    const int kbase = kb * 16;
    const int ubase = ub * 64;

    const bool isx = (kbase < UDIM);
    const int klocal = isx ? kbase : (kbase - UDIM);
    const float* Wg[4];
    Wg[0] = isx ? wxf : whf;
    Wg[1] = isx ? wxi : whi;
    Wg[2] = isx ? wxo : who;
    Wg[3] = isx ? wxg : whg;

    const int r = tid >> 4, q = tid & 15;
#pragma unroll
    for (int g = 0; g < 4; g++) {
        float4 v = *(const float4*)(Wg[g] + (size_t)(klocal + r) * UDIM +
                                    ubase + q * 4);
        float* d = s_w + (r * 4 + g) * WLD + q * 4;
        d[0] = v.x; d[1] = v.y; d[2] = v.z; d[3] = v.w;
    }
    __syncthreads();

#pragma unroll
    for (int i = 0; i < 2; i++) {
        int o = tid + 256 * i;
        int lane = o & 31;
        int nbpl = o >> 5;                   // 0..15
        int kq = lane & 3, nq = lane >> 2;
        int c0 = nbpl * 16 + nq;
        int g = c0 & 3;
        int u0 = c0 >> 2;
        uint4 v;
        v.x = packh2(s_w[((2 * kq) * 4 + g) * WLD + u0],
                     s_w[((2 * kq + 1) * 4 + g) * WLD + u0]);
        v.y = packh2(s_w[((2 * kq + 8) * 4 + g) * WLD + u0],
                     s_w[((2 * kq + 9) * 4 + g) * WLD + u0]);
        v.z = packh2(s_w[((2 * kq) * 4 + g) * WLD + u0 + 2],
                     s_w[((2 * kq + 1) * 4 + g) * WLD + u0 + 2]);
        v.w = packh2(s_w[((2 * kq + 8) * 4 + g) * WLD + u0 + 2],
                     s_w[((2 * kq + 9) * 4 + g) * WLD + u0 + 2]);
        int nbp = ub * 16 + nbpl;
        *(uint4*)(g_Bp + ((size_t)kb * NBPTOT + nbp) * 128 + lane * 4) = v;
    }
}

__global__ void __launch_bounds__(256) pack_AW_kernel(
    const float* __restrict__ x, const float* __restrict__ h,
    const float* __restrict__ wxf, const float* __restrict__ wxi,
    const float* __restrict__ wxo, const float* __restrict__ wxg,
    const float* __restrict__ whf, const float* __restrict__ whi,
    const float* __restrict__ who, const float* __restrict__ whg)
{
    __shared__ float s_w[64 * WLD];
    if (blockIdx.x < NA_BLOCKS)
        pack_A_body(x, h, blockIdx.x);
    else
        pack_W_body(s_w, wxf, wxi, wxo, wxg, whf, whi, who, whg,
                    blockIdx.x - NA_BLOCKS);
}

// ---------------------------------------------------------------- GEMM
__device__ __forceinline__ void load_stage(uint32_t sbase, int slot, int ch,
                                           int tid, int mb0, int nbp0)
{
    uint32_t sa = sbase + slot * STAGE_BYTES;
    uint32_t sb = sa + SA_STAGE;
    const int k16 = ch * 2;
    const uint32_t* a0 = g_Ap + (size_t)k16 * AK16 + mb0 * 128;
    const uint32_t* b0 = g_Bp + (size_t)k16 * BK16 + nbp0 * 128;
#pragma unroll
    for (int j = 0; j < 2; j++) {          // 2 k16 slabs, 4KB each operand
        cp16(sa + j * 4096 + tid * 16,        a0 + (size_t)j * AK16 + tid * 4);
        cp16(sa + j * 4096 + 2048 + tid * 16, a0 + (size_t)j * AK16 + 512 + tid * 4);
        cp16(sb + j * 4096 + tid * 16,        b0 + (size_t)j * BK16 + tid * 4);
        cp16(sb + j * 4096 + 2048 + tid * 16, b0 + (size_t)j * BK16 + 512 + tid * 4);
    }
}

// One TK=32 chunk: ks=0 uses buf0 (pre-primed), prefetches slab1 into buf1;
// ks=1 uses buf1, prefetches next chunk's slab0 into buf0 (if PF).
__device__ __forceinline__ void compute_chunk(
    uint32_t sa, uint32_t sa_n, bool pf_next,
    uint32_t a_off, uint32_t b_off,
    uint32_t (&a)[2][4][4], uint32_t (&b)[2][8][2],
    float (&acc)[4][8][4])
{
    const uint32_t sb = sa + SA_STAGE;
    const uint32_t sb_n = sa_n + SA_STAGE;

    // ks = 0
#pragma unroll
    for (int mf = 0; mf < 4; mf++)
        lds128(a[1][mf], sa + 4096 + mf * 512 + a_off);
#pragma unroll
    for (int p = 0; p < 4; p++)
        lds128(&b[1][2 * p][0], sb + 4096 + p * 512 + b_off);
#pragma unroll
    for (int mf = 0; mf < 4; mf++)
#pragma unroll
        for (int nf = 0; nf < 8; nf++)
            mma16(acc[mf][nf], a[0][mf], b[0][nf]);

    // ks = 1
    if (pf_next) {
#pragma unroll
        for (int mf = 0; mf < 4; mf++)
            lds128(a[0][mf], sa_n + mf * 512 + a_off);
#pragma unroll
        for (int p = 0; p < 4; p++)
            lds128(&b[0][2 * p][0], sb_n + p * 512 + b_off);
    }
#pragma unroll
    for (int mf = 0; mf < 4; mf++)
#pragma unroll
        for (int nf = 0; nf < 8; nf++)
            mma16(acc[mf][nf], a[1][mf], b[1][nf]);
}

__global__ void __launch_bounds__(NTHREADS, 2) lstm_gemm_kernel(
    const float* __restrict__ cin,
    const float* __restrict__ bfp, const float* __restrict__ bip,
    const float* __restrict__ bop, const float* __restrict__ bgp,
    float* __restrict__ out)
{
    extern __shared__ char smem[];
    const uint32_t sbase = smem_u32(smem);
    const int tid = threadIdx.x;
    const int wid = tid >> 5;
    const int lane = tid & 31;
    const int mt = blockIdx.x & 31;          // m fastest: A stays L2-resident
    const int nt = blockIdx.x >> 5;          // 0..63
    const int mb0 = mt * 8;
    const int nbp0 = nt * 8;

    const int wmi = wid & 1;                 // warp m index (64-row tile)
    const int wni = wid >> 1;                // warp n index (64-col tile)
    const uint32_t a_off = (uint32_t)wmi * 2048 + lane * 16;
    const uint32_t b_off = (uint32_t)wni * 2048 + lane * 16;

    float acc[4][8][4];
#pragma unroll
    for (int mf = 0; mf < 4; mf++)
#pragma unroll
        for (int nf = 0; nf < 8; nf++)
#pragma unroll
            for (int r = 0; r < 4; r++) acc[mf][nf][r] = 0.f;

    // prologue: chunks 0..3 in flight (slots 0..3), one group each
#pragma unroll
    for (int s = 0; s < 4; s++) {
        load_stage(sbase, s, s, tid, mb0, nbp0);
        cp_commit();
    }

    uint32_t a[2][4][4];
    uint32_t b[2][8][2];

    // Main loop: one barrier per TWO chunks.
    //  even kt: cp_wait<1> (completes G(kt+1),G(kt+2); both committed >=3
    //           bodies ago -> no drain), barrier (publishes stages <= kt+2;
    //           all threads past compute kt-1), load chunk kt+4, compute kt.
    //  odd  kt: load chunk kt+5 (slot last read at kt-1: safe by the even
    //           barrier), compute kt+1 (published), no wait/barrier.
    int cs = 0;          // compute slot (kt % 6)
    int ls = 4;          // load slot ((kt+4) % 6)
    for (int kt = 0; kt < CHUNKS; kt += 2) {
        cp_wait<1>();
        __syncthreads();
        if (kt == 0) {   // prime buf0 with (chunk 0, slab 0) fragments
#pragma unroll
            for (int mf = 0; mf < 4; mf++)
                lds128(a[0][mf], sbase + mf * 512 + a_off);
#pragma unroll
            for (int p = 0; p < 4; p++)
                lds128(&b[0][2 * p][0], sbase + SA_STAGE + p * 512 + b_off);
        }

        // even body
        if (kt + 4 < CHUNKS) load_stage(sbase, ls, kt + 4, tid, mb0, nbp0);
        cp_commit();
        {
            const int ns = (cs == NSLOTS - 1) ? 0 : cs + 1;
            compute_chunk(sbase + cs * STAGE_BYTES, sbase + ns * STAGE_BYTES,
                          true, a_off, b_off, a, b, acc);
            cs = ns;
        }
        ls = (ls == NSLOTS - 1) ? 0 : ls + 1;

        // odd body
        if (kt + 5 < CHUNKS) load_stage(sbase, ls, kt + 5, tid, mb0, nbp0);
        cp_commit();
        {
            const int ns = (cs == NSLOTS - 1) ? 0 : cs + 1;
            compute_chunk(sbase + cs * STAGE_BYTES, sbase + ns * STAGE_BYTES,
                          kt + 2 < CHUNKS, a_off, b_off, a, b, acc);
            cs = ns;
        }
        ls = (ls == NSLOTS - 1) ? 0 : ls + 1;
    }

    cp_wait<0>();
    __syncthreads();     // pipeline done; reuse smem for z tile

    // ---- epilogue: single 128x128 z tile through smem ----
    float* s_z = (float*)smem;
    const int gq = lane >> 2, kq = lane & 3;
    const int m0 = mt * TM;
    const size_t HC = (size_t)MTOT * UDIM;

#pragma unroll
    for (int mf = 0; mf < 4; mf++)
#pragma unroll
        for (int nf = 0; nf < 8; nf++) {
            int row = wmi * 64 + mf * 16 + gq;
            int col = wni * 64 + nf * 8 + 2 * kq;
            *(float2*)(s_z + row * ZLD + col) =
                make_float2(acc[mf][nf][0], acc[mf][nf][1]);
            *(float2*)(s_z + (row + 8) * ZLD + col) =
                make_float2(acc[mf][nf][2], acc[mf][nf][3]);
        }
    __syncthreads();

    const int ul = tid & 31;                 // unit lane (32 units per CTA)
    const int rb = tid >> 5;                 // 4 row blocks of 32 rows
    const int u = nt * 32 + ul;
    const float bf = __ldg(bfp + u);
    const float bi = __ldg(bip + u);
    const float bo = __ldg(bop + u);
    const float bg = __ldg(bgp + u);

#pragma unroll 4
    for (int rr = 0; rr < 32; rr++) {
        int row = rb * 32 + rr;
        float4 z = *(const float4*)(s_z + row * ZLD + 4 * ul);
        size_t g = (size_t)(m0 + row) * UDIM + u;
        float fg = fsig(z.x + bf);
        float ig = fsig(z.y + bi);
        float og = fsig(z.z + bo);
        float gg = ftanh(z.w + bg);
        float cn = fg * __ldcs(cin + g) + ig * gg;
        float hn = og * ftanh(cn);
        __stcs(out + g, hn);          // h_new (streaming store)
        __stcs(out + HC + g, cn);     // c_new
    }
}

// ---------------------------------------------------------------- launch
extern "C" void kernel_launch(void* const* d_in, const int* in_sizes, int n_in,
                              void* d_out, int out_size) {
    (void)in_sizes; (void)n_in; (void)out_size;
    const float* x   = (const float*)d_in[0];
    const float* h   = (const float*)d_in[1];
    const float* c   = (const float*)d_in[2];
    const float* Wxf = (const float*)d_in[3];
    const float* Wxi = (const float*)d_in[4];
    const float* Wxo = (const float*)d_in[5];
    const float* Wxg = (const float*)d_in[6];
    const float* bf  = (const float*)d_in[7];
    const float* bi  = (const float*)d_in[8];
    const float* bo  = (const float*)d_in[9];
    const float* bg  = (const float*)d_in[10];
    const float* Whf = (const float*)d_in[11];
    const float* Whi = (const float*)d_in[12];
    const float* Who = (const float*)d_in[13];
    const float* Whg = (const float*)d_in[14];
    float* out = (float*)d_out;

    static int smem_set = 0;
    if (!smem_set) {
        cudaFuncSetAttribute(lstm_gemm_kernel,
                             cudaFuncAttributeMaxDynamicSharedMemorySize,
                             SMEM_BYTES);
        smem_set = 1;
    }

    pack_AW_kernel<<<NA_BLOCKS + NW_BLOCKS, 256>>>(
        x, h, Wxf, Wxi, Wxo, Wxg, Whf, Whi, Who, Whg);
    lstm_gemm_kernel<<<(MTOT / TM) * (NTOT / TN), NTHREADS, SMEM_BYTES>>>(
        c, bf, bi, bo, bg, out);
}

// round 15
// speedup vs baseline: 1.1064x; 1.1064x over previous
#include <cuda_runtime.h>
#include <cuda_fp16.h>
#include <cstdint>

// ============================================================================
// LSTM cell, base sm_103 ISA. fp16 mma.sync m16n8k16, cp.async 4-slot TK=48,
// SINGLE barrier per k-chunk (distance-2 slot reuse makes load-first safe),
// fragment-packed operands, register double-buffered fragments with
// cross-stage prefetch. CTA 128x128, 128 threads, warp tile 64x64, 2 CTAs/SM.
// Fused gate epilogue (fast sigmoid/tanh).
// [R15: verified-best R13 configuration, locked in after R14 regression.]
//
// z[4096, 8192] = A[4096, 4096] @ B[4096, 8192]
//   A = [x | h], B[k][4u+g] = W{x,h}{f,i,o,g}[k][u]  (gate-interleaved)
// K padded with 2 zero k16-slices so 86 stages of TK=48 cover K=4096.
// ============================================================================

#define MTOT 4096
#define KTOT 4096
#define NTOT 8192
#define UDIM 2048

#define TM 128
#define TN 128
#define NTHREADS 128

#define MBTOT 256              // MTOT/16
#define NBPTOT 512             // NTOT/16 (n-fragment pairs)
#define K16TOT 256             // KTOT/16
#define K16PAD 258             // +2 zero slices (pad to 86*3)
#define KT 86                  // number of TK=48 stages

#define AK16 (MBTOT * 128)     // uint32 stride per k16 in g_Ap
#define BK16 (NBPTOT * 128)    // uint32 stride per k16 in g_Bp

#define SA_STAGE 12288         // 3 k16 * 8 mb * 512 B
#define SB_STAGE 12288         // 3 k16 * 8 nbp * 512 B
#define STAGE_BYTES (SA_STAGE + SB_STAGE)      // 24576
#define PIPE_BYTES (4 * STAGE_BYTES)           // 98304 (4 slots)
#define ZLD 132                                 // z tile: 128*132*4 = 67584
#define SMEM_BYTES PIPE_BYTES

// Fragment-packed fp16 operands (uint32 = f16x2). Zero-padded k16 256..257
// (device globals are zero-initialized; pack kernels write only 0..255).
static __device__ __align__(16) uint32_t g_Ap[(size_t)K16PAD * AK16];
static __device__ __align__(16) uint32_t g_Bp[(size_t)K16PAD * BK16];

// ---------------------------------------------------------------- helpers
__device__ __forceinline__ uint32_t smem_u32(const void* p) {
    uint32_t a;
    asm("{ .reg .u64 t; cvta.to.shared.u64 t, %1; cvt.u32.u64 %0, t; }"
        : "=r"(a) : "l"(p));
    return a;
}

__device__ __forceinline__ uint32_t packh2(float lo, float hi) {
    __half2 h = __floats2half2_rn(lo, hi);
    return *reinterpret_cast<uint32_t*>(&h);
}

__device__ __forceinline__ void cp16(uint32_t dst, const void* src) {
    asm volatile("cp.async.cg.shared.global [%0], [%1], 16;"
                 :: "r"(dst), "l"(src) : "memory");
}
__device__ __forceinline__ void cp_commit() {
    asm volatile("cp.async.commit_group;" ::: "memory");
}
template <int N>
__device__ __forceinline__ void cp_wait() {
    asm volatile("cp.async.wait_group %0;" :: "n"(N) : "memory");
}

__device__ __forceinline__ void mma16(float* d, const uint32_t* a, const uint32_t* b) {
    asm volatile(
        "mma.sync.aligned.m16n8k16.row.col.f32.f16.f16.f32 "
        "{%0,%1,%2,%3}, {%4,%5,%6,%7}, {%8,%9}, {%0,%1,%2,%3};"
        : "+f"(d[0]), "+f"(d[1]), "+f"(d[2]), "+f"(d[3])
        : "r"(a[0]), "r"(a[1]), "r"(a[2]), "r"(a[3]), "r"(b[0]), "r"(b[1]));
}

__device__ __forceinline__ void lds128(uint32_t* r, uint32_t addr) {
    asm volatile("ld.shared.v4.b32 {%0,%1,%2,%3}, [%4];"
                 : "=r"(r[0]), "=r"(r[1]), "=r"(r[2]), "=r"(r[3]) : "r"(addr));
}

__device__ __forceinline__ float fsig(float z) {        // fast sigmoid
    return __fdividef(1.f, 1.f + __expf(-z));
}
__device__ __forceinline__ float ftanh(float z) {       // tanh = 2*sig(2z)-1
    return __fmaf_rn(2.f, __fdividef(1.f, 1.f + __expf(-2.f * z)), -1.f);
}

// ---------------------------------------------------------------- prepasses
#define NA_BLOCKS 8192
#define NW_BLOCKS 8192
#define WLD 65

__device__ void pack_A_body(const float* __restrict__ x,
                            const float* __restrict__ h, int blk)
{
    uint32_t t = blk * 256 + threadIdx.x;
    int lane = t & 31;
    int mb = (t >> 5) & 255;
    int k16 = t >> 13;                   // 0..255
    int kq = lane & 3, gq = lane >> 2;
    int m = mb * 16 + gq;
    int k = k16 * 16 + 2 * kq;
    const float* src = (k < UDIM) ? (x + k) : (h + (k - UDIM));
    float2 p0 = *(const float2*)(src + (size_t)m * UDIM);
    float2 p1 = *(const float2*)(src + (size_t)(m + 8) * UDIM);
    float2 p2 = *(const float2*)(src + (size_t)m * UDIM + 8);
    float2 p3 = *(const float2*)(src + (size_t)(m + 8) * UDIM + 8);
    uint4 u;
    u.x = packh2(p0.x, p0.y);
    u.y = packh2(p1.x, p1.y);
    u.z = packh2(p2.x, p2.y);
    u.w = packh2(p3.x, p3.y);
    *(uint4*)(g_Ap + (size_t)t * 4) = u;
}

__device__ void pack_W_body(
    float* s_w,
    const float* __restrict__ wxf, const float* __restrict__ wxi,
    const float* __restrict__ wxo, const float* __restrict__ wxg,
    const float* __restrict__ whf, const float* __restrict__ whi,
    const float* __restrict__ who, const float* __restrict__ whg, int blk)
{
    const int tid = threadIdx.x;
    const int kb = blk & 255;                // 256 k16 blocks
    const int ub = blk >> 8;                 // 32 unit-blocks of 64
    const int kbase = kb * 16;
    const int ubase = ub * 64;

    const bool isx = (kbase < UDIM);
    const int klocal = isx ? kbase : (kbase - UDIM);
    const float* Wg[4];
    Wg[0] = isx ? wxf : whf;
    Wg[1] = isx ? wxi : whi;
    Wg[2] = isx ? wxo : who;
    Wg[3] = isx ? wxg : whg;

    const int r = tid >> 4, q = tid & 15;
#pragma unroll
    for (int g = 0; g < 4; g++) {
        float4 v = *(const float4*)(Wg[g] + (size_t)(klocal + r) * UDIM +
                                    ubase + q * 4);
        float* d = s_w + (r * 4 + g) * WLD + q * 4;
        d[0] = v.x; d[1] = v.y; d[2] = v.z; d[3] = v.w;
    }
    __syncthreads();

#pragma unroll
    for (int i = 0; i < 2; i++) {
        int o = tid + 256 * i;
        int lane = o & 31;
        int nbpl = o >> 5;                   // 0..15
        int kq = lane & 3, nq = lane >> 2;
        int c0 = nbpl * 16 + nq;
        int g = c0 & 3;
        int u0 = c0 >> 2;
        uint4 v;
        v.x = packh2(s_w[((2 * kq) * 4 + g) * WLD + u0],
                     s_w[((2 * kq + 1) * 4 + g) * WLD + u0]);
        v.y = packh2(s_w[((2 * kq + 8) * 4 + g) * WLD + u0],
                     s_w[((2 * kq + 9) * 4 + g) * WLD + u0]);
        v.z = packh2(s_w[((2 * kq) * 4 + g) * WLD + u0 + 2],
                     s_w[((2 * kq + 1) * 4 + g) * WLD + u0 + 2]);
        v.w = packh2(s_w[((2 * kq + 8) * 4 + g) * WLD + u0 + 2],
                     s_w[((2 * kq + 9) * 4 + g) * WLD + u0 + 2]);
        int nbp = ub * 16 + nbpl;
        *(uint4*)(g_Bp + ((size_t)kb * NBPTOT + nbp) * 128 + lane * 4) = v;
    }
}

__global__ void __launch_bounds__(256) pack_AW_kernel(
    const float* __restrict__ x, const float* __restrict__ h,
    const float* __restrict__ wxf, const float* __restrict__ wxi,
    const float* __restrict__ wxo, const float* __restrict__ wxg,
    const float* __restrict__ whf, const float* __restrict__ whi,
    const float* __restrict__ who, const float* __restrict__ whg)
{
    __shared__ float s_w[64 * WLD];
    if (blockIdx.x < NA_BLOCKS)
        pack_A_body(x, h, blockIdx.x);
    else
        pack_W_body(s_w, wxf, wxi, wxo, wxg, whf, whi, who, whg,
                    blockIdx.x - NA_BLOCKS);
}

// ---------------------------------------------------------------- GEMM
__device__ __forceinline__ void load_stage(uint32_t sbase, int slot, int st,
                                           int tid, int mb0, int nbp0)
{
    uint32_t sa = sbase + slot * STAGE_BYTES;
    uint32_t sb = sa + SA_STAGE;
    const int k16 = st * 3;
    const uint32_t* a0 = g_Ap + (size_t)k16 * AK16 + mb0 * 128;
    const uint32_t* b0 = g_Bp + (size_t)k16 * BK16 + nbp0 * 128;
#pragma unroll
    for (int j = 0; j < 3; j++) {          // 3 k16 slabs, 4KB each operand
        cp16(sa + j * 4096 + tid * 16,        a0 + (size_t)j * AK16 + tid * 4);
        cp16(sa + j * 4096 + 2048 + tid * 16, a0 + (size_t)j * AK16 + 512 + tid * 4);
        cp16(sb + j * 4096 + tid * 16,        b0 + (size_t)j * BK16 + tid * 4);
        cp16(sb + j * 4096 + 2048 + tid * 16, b0 + (size_t)j * BK16 + 512 + tid * 4);
    }
}

// One TK=48 chunk. PAR = (3*kt)&1 resolves the register-ring parity
// (3 ks per chunk flips parity each chunk; kt loop is unrolled by 2).
template <int PAR>
__device__ __forceinline__ void kt_body(
    int kt, uint32_t sbase, int tid, int mb0, int nbp0,
    uint32_t a_off, uint32_t b_off,
    uint32_t (&a)[2][4][4], uint32_t (&b)[2][8][2],
    float (&acc)[4][8][4])
{
    // Single-barrier ordering (safe: written slot (kt+2)&3 was last read at
    // kt-2, and every thread passed the kt-1 barrier before this load):
    if (kt + 2 < KT) load_stage(sbase, (kt + 2) & 3, kt + 2, tid, mb0, nbp0);
    cp_commit();
    cp_wait<1>();        // stage kt+1 complete (self); kt+2 stays in flight
    __syncthreads();     // publish kt+1 to all; lockstep for slot safety

    const uint32_t sa = sbase + (kt & 3) * STAGE_BYTES;
    const uint32_t sb = sa + SA_STAGE;
    const uint32_t sa_n = sbase + ((kt + 1) & 3) * STAGE_BYTES;
    const uint32_t sb_n = sa_n + SA_STAGE;

#pragma unroll
    for (int ks = 0; ks < 3; ks++) {
        const int cur = (ks + PAR) & 1, nxt = cur ^ 1;
        if (ks < 2) {        // prefetch next slab of this stage
#pragma unroll
            for (int mf = 0; mf < 4; mf++)
                lds128(a[nxt][mf], sa + (ks + 1) * 4096 + mf * 512 + a_off);
#pragma unroll
            for (int p = 0; p < 4; p++)
                lds128(&b[nxt][2 * p][0], sb + (ks + 1) * 4096 + p * 512 + b_off);
        } else if (kt + 1 < KT) {   // prefetch slab 0 of NEXT stage
#pragma unroll
            for (int mf = 0; mf < 4; mf++)
                lds128(a[nxt][mf], sa_n + mf * 512 + a_off);
#pragma unroll
            for (int p = 0; p < 4; p++)
                lds128(&b[nxt][2 * p][0], sb_n + p * 512 + b_off);
        }
#pragma unroll
        for (int mf = 0; mf < 4; mf++)
#pragma unroll
            for (int nf = 0; nf < 8; nf++)
                mma16(acc[mf][nf], a[cur][mf], b[cur][nf]);
    }
}

__global__ void __launch_bounds__(NTHREADS, 2) lstm_gemm_kernel(
    const float* __restrict__ cin,
    const float* __restrict__ bfp, const float* __restrict__ bip,
    const float* __restrict__ bop, const float* __restrict__ bgp,
    float* __restrict__ out)
{
    extern __shared__ char smem[];
    const uint32_t sbase = smem_u32(smem);
    const int tid = threadIdx.x;
    const int wid = tid >> 5;
    const int lane = tid & 31;
    const int mt = blockIdx.x & 31;          // m fastest: A stays L2-resident
    const int nt = blockIdx.x >> 5;          // 0..63
    const int mb0 = mt * 8;
    const int nbp0 = nt * 8;

    const int wmi = wid & 1;                 // warp m index (64-row tile)
    const int wni = wid >> 1;                // warp n index (64-col tile)
    const uint32_t a_off = (uint32_t)wmi * 2048 + lane * 16;
    const uint32_t b_off = (uint32_t)wni * 2048 + lane * 16;

    float acc[4][8][4];
#pragma unroll
    for (int mf = 0; mf < 4; mf++)
#pragma unroll
        for (int nf = 0; nf < 8; nf++)
#pragma unroll
            for (int r = 0; r < 4; r++) acc[mf][nf][r] = 0.f;

    // prologue: stages 0 and 1 in flight
    load_stage(sbase, 0, 0, tid, mb0, nbp0);
    cp_commit();
    load_stage(sbase, 1, 1, tid, mb0, nbp0);
    cp_commit();
    cp_wait<1>();            // stage 0 complete (self)
    __syncthreads();         // visible to all

    uint32_t a[2][4][4];
    uint32_t b[2][8][2];

    // prime buffer 0 with (stage 0, ks=0) fragments
#pragma unroll
    for (int mf = 0; mf < 4; mf++)
        lds128(a[0][mf], sbase + mf * 512 + a_off);
#pragma unroll
    for (int p = 0; p < 4; p++)
        lds128(&b[0][2 * p][0], sbase + SA_STAGE + p * 512 + b_off);

    for (int kt = 0; kt < KT; kt += 2) {     // KT=86 (even)
        kt_body<0>(kt,     sbase, tid, mb0, nbp0, a_off, b_off, a, b, acc);
        kt_body<1>(kt + 1, sbase, tid, mb0, nbp0, a_off, b_off, a, b, acc);
    }

    cp_wait<0>();
    __syncthreads();     // pipeline done; reuse smem for z tile

    // ---- epilogue: single 128x128 z tile through smem ----
    float* s_z = (float*)smem;
    const int gq = lane >> 2, kq = lane & 3;
    const int m0 = mt * TM;
    const size_t HC = (size_t)MTOT * UDIM;

#pragma unroll
    for (int mf = 0; mf < 4; mf++)
#pragma unroll
        for (int nf = 0; nf < 8; nf++) {
            int row = wmi * 64 + mf * 16 + gq;
            int col = wni * 64 + nf * 8 + 2 * kq;
            *(float2*)(s_z + row * ZLD + col) =
                make_float2(acc[mf][nf][0], acc[mf][nf][1]);
            *(float2*)(s_z + (row + 8) * ZLD + col) =
                make_float2(acc[mf][nf][2], acc[mf][nf][3]);
        }
    __syncthreads();

    const int ul = tid & 31;                 // unit lane (32 units per CTA)
    const int rb = tid >> 5;                 // 4 row blocks of 32 rows
    const int u = nt * 32 + ul;
    const float bf = __ldg(bfp + u);
    const float bi = __ldg(bip + u);
    const float bo = __ldg(bop + u);
    const float bg = __ldg(bgp + u);

#pragma unroll 4
    for (int rr = 0; rr < 32; rr++) {
        int row = rb * 32 + rr;
        float4 z = *(const float4*)(s_z + row * ZLD + 4 * ul);
        size_t g = (size_t)(m0 + row) * UDIM + u;
        float fg = fsig(z.x + bf);
        float ig = fsig(z.y + bi);
        float og = fsig(z.z + bo);
        float gg = ftanh(z.w + bg);
        float cn = fg * __ldcs(cin + g) + ig * gg;
        float hn = og * ftanh(cn);
        __stcs(out + g, hn);          // h_new (streaming store)
        __stcs(out + HC + g, cn);     // c_new
    }
}

// ---------------------------------------------------------------- launch
extern "C" void kernel_launch(void* const* d_in, const int* in_sizes, int n_in,
                              void* d_out, int out_size) {
    (void)in_sizes; (void)n_in; (void)out_size;
    const float* x   = (const float*)d_in[0];
    const float* h   = (const float*)d_in[1];
    const float* c   = (const float*)d_in[2];
    const float* Wxf = (const float*)d_in[3];
    const float* Wxi = (const float*)d_in[4];
    const float* Wxo = (const float*)d_in[5];
    const float* Wxg = (const float*)d_in[6];
    const float* bf  = (const float*)d_in[7];
    const float* bi  = (const float*)d_in[8];
    const float* bo  = (const float*)d_in[9];
    const float* bg  = (const float*)d_in[10];
    const float* Whf = (const float*)d_in[11];
    const float* Whi = (const float*)d_in[12];
    const float* Who = (const float*)d_in[13];
    const float* Whg = (const float*)d_in[14];
    float* out = (float*)d_out;

    static int smem_set = 0;
    if (!smem_set) {
        cudaFuncSetAttribute(lstm_gemm_kernel,
                             cudaFuncAttributeMaxDynamicSharedMemorySize,
                             SMEM_BYTES);
        smem_set = 1;
    }

    pack_AW_kernel<<<NA_BLOCKS + NW_BLOCKS, 256>>>(
        x, h, Wxf, Wxi, Wxo, Wxg, Whf, Whi, Who, Whg);
    lstm_gemm_kernel<<<(MTOT / TM) * (NTOT / TN), NTHREADS, SMEM_BYTES>>>(
        c, bf, bi, bo, bg, out);
}